// round 17
// baseline (speedup 1.0000x reference)
#include <cuda_runtime.h>

// 2-layer LSTM (HID=10) + linear head, B=2048, T=1024, future=64.
// Round 17: R16 (best, 299.7us) with two subtractive changes:
//  (1) x(t+1) folded into the h1 broadcast vector (slot[10] of the 12-wide
//      h1 slot; slot[11] zeroed once). load_vec12 is still 3 LDS; layer-1
//      gate init becomes a 6th FFMA2 pair with weight (wih1,0). Removes
//      per-lane x LDS + 4 FMA inits + pack MOVs.
//  (2) manual 2x unroll with role-swapped G/H gate registers — removes the
//      8 G=N register copies per step. Accumulators init by 3-address
//      first-FFMA2 from constant b1/b2 pairs.
// Ordering, history flush, tail, grid identical to R16.

#define HID 10
#define T_FIXED 1024

typedef unsigned long long u64;

__device__ __forceinline__ u64 pack2(float lo, float hi) {
    u64 d; asm("mov.b64 %0, {%1, %2};" : "=l"(d) : "f"(lo), "f"(hi)); return d;
}
__device__ __forceinline__ void unpack2(u64 d, float& lo, float& hi) {
    asm("mov.b64 {%0, %1}, %2;" : "=f"(lo), "=f"(hi) : "l"(d));
}
__device__ __forceinline__ u64 ffma2(u64 a, u64 b, u64 c) {
    u64 d; asm("fma.rn.f32x2 %0, %1, %2, %3;" : "=l"(d) : "l"(a), "l"(b), "l"(c));
    return d;
}
__device__ __forceinline__ float psum(u64 a) {
    float l, h; unpack2(a, l, h); return l + h;
}
__device__ __forceinline__ float tanh_hw(float v) {
    float r; asm("tanh.approx.f32 %0, %1;" : "=f"(r) : "f"(v)); return r;
}

// Gates gi,gf,go arrive PRE-HALVED (weights/biases scaled by 0.5).
__device__ __forceinline__ float cell_update_h(
    float gi_h, float gf_h, float gg, float go_h, float& c)
{
    float si = fmaf(tanh_hw(gi_h), 0.5f, 0.5f);
    float sf = fmaf(tanh_hw(gf_h), 0.5f, 0.5f);
    float so = fmaf(tanh_hw(go_h), 0.5f, 0.5f);
    float tg = tanh_hw(gg);
    c = fmaf(sf, c, si * tg);
    return so * tanh_hw(c);
}

// Volatile + memory-clobber shared loads (R13/R16 proven ordering).
__device__ __forceinline__ void load_vec10(const float* p, u64* v) {
    unsigned a = (unsigned)__cvta_generic_to_shared(p);
    asm volatile("ld.shared.v2.b64 {%0,%1}, [%2];"
                 : "=l"(v[0]), "=l"(v[1]) : "r"(a) : "memory");
    asm volatile("ld.shared.v2.b64 {%0,%1}, [%2];"
                 : "=l"(v[2]), "=l"(v[3]) : "r"(a + 16) : "memory");
    asm volatile("ld.shared.b64 %0, [%1];"
                 : "=l"(v[4]) : "r"(a + 32) : "memory");
}
__device__ __forceinline__ void load_vec12(const float* p, u64* v) {
    unsigned a = (unsigned)__cvta_generic_to_shared(p);
    asm volatile("ld.shared.v2.b64 {%0,%1}, [%2];"
                 : "=l"(v[0]), "=l"(v[1]) : "r"(a) : "memory");
    asm volatile("ld.shared.v2.b64 {%0,%1}, [%2];"
                 : "=l"(v[2]), "=l"(v[3]) : "r"(a + 16) : "memory");
    asm volatile("ld.shared.v2.b64 {%0,%1}, [%2];"
                 : "=l"(v[4]), "=l"(v[5]) : "r"(a + 32) : "memory");
}

// Per-warp smem layout (floats):
//   h1[3][12] (slot: h0..h9, x, 0) | h2hist[16][3][12] | x[3][20]
#define SW_H1   0
#define SW_HIST 36
#define SW_X    612
#define SW_WARP 672        // 2688 B per warp, 16B-divisible

__global__ void __launch_bounds__(128, 1)
lstm2_seq_kernel(
    const float* __restrict__ x,
    const float* __restrict__ W_ih1, const float* __restrict__ W_hh1,
    const float* __restrict__ b_ih1, const float* __restrict__ b_hh1,
    const float* __restrict__ W_ih2, const float* __restrict__ W_hh2,
    const float* __restrict__ b_ih2, const float* __restrict__ b_hh2,
    const float* __restrict__ W_lin, const float* __restrict__ b_lin,
    float* __restrict__ out,
    int B, int T, int outT)
{
    __shared__ __align__(16) float sm[4 * SW_WARP];

    const int lane   = threadIdx.x & 31;
    const int warpIn = threadIdx.x >> 5;
    const int warpGl = blockIdx.x * 4 + warpIn;
    const int g      = lane / 10;          // 0..2 active groups; 3 = idle
    const int k      = lane - g * 10;      // unit index within group
    const int gc     = (g < 3) ? g : 0;
    const int warpB0 = warpGl * 3;
    const int b      = warpB0 + gc;
    const bool alane = (g < 3) && (b < B);
    float* sw = sm + warpIn * SW_WARP;

    // ---- per-lane weights; i/f/o rows (q != 2) pre-scaled by 0.5 ----
    float wih1[4], b1[4], b2[4];
    u64 whh1[4][5], wih2[4][5], whh2[4][5], wlinp[5];
    u64 wih1p[4], b1p[4], b2p[4];
#pragma unroll
    for (int q = 0; q < 4; q++) {
        const float sc = (q == 2) ? 1.0f : 0.5f;
        const int r = q * HID + k;
        wih1[q] = (alane ? W_ih1[r] : 0.0f) * sc;
        b1[q]   = (alane ? (b_ih1[r] + b_hh1[r]) : 0.0f) * sc;
        b2[q]   = (alane ? (b_ih2[r] + b_hh2[r]) : 0.0f) * sc;
        wih1p[q] = pack2(wih1[q], 0.0f);
        b1p[q]   = pack2(b1[q], 0.0f);
        b2p[q]   = pack2(b2[q], 0.0f);
#pragma unroll
        for (int p = 0; p < 5; p++) {
            whh1[q][p] = pack2((alane ? W_hh1[r*HID+2*p]   : 0.0f) * sc,
                               (alane ? W_hh1[r*HID+2*p+1] : 0.0f) * sc);
            wih2[q][p] = pack2((alane ? W_ih2[r*HID+2*p]   : 0.0f) * sc,
                               (alane ? W_ih2[r*HID+2*p+1] : 0.0f) * sc);
            whh2[q][p] = pack2((alane ? W_hh2[r*HID+2*p]   : 0.0f) * sc,
                               (alane ? W_hh2[r*HID+2*p+1] : 0.0f) * sc);
        }
    }
#pragma unroll
    for (int p = 0; p < 5; p++) wlinp[p] = pack2(W_lin[2*p], W_lin[2*p+1]);
    const float blin = b_lin[0];

    float c1 = 0.0f, c2 = 0.0f;

    // zero the h1 region (slot[11] zeros are load-bearing for the 6th pair)
    for (int i = lane; i < 36; i += 32) sw[SW_H1 + i] = 0.0f;

    // ---- x staging helpers (R16) ----
    float xr0 = 0.0f, xr1 = 0.0f;
    auto ldg_chunk = [&](int t0, float& r0, float& r1) {
        int g0_ = lane >> 4, c0_ = lane & 15;
        int bb0 = warpB0 + g0_;
        r0 = (bb0 < B) ? x[(size_t)bb0 * T + t0 + c0_] : 0.0f;
        int bb1 = warpB0 + 2;
        r1 = (lane < 16 && bb1 < B) ? x[(size_t)bb1 * T + t0 + lane] : 0.0f;
    };
    auto sts_chunk = [&](float r0, float r1) {
        sw[SW_X + (lane >> 4) * 20 + (lane & 15)] = r0;
        if (lane < 16) sw[SW_X + 2 * 20 + lane] = r1;
    };
    auto flush_y = [&](int t0) {
#pragma unroll
        for (int r2 = 0; r2 < 2; r2++) {
            int idx = lane + r2 * 32;
            if (idx < 48) {
                int s  = idx & 15;
                int gb = idx >> 4;                 // 0..2
                u64 hv[5];
                load_vec10(sw + SW_HIST + s * 36 + gb * 12, hv);
                u64 Y = pack2(blin, 0.0f);
#pragma unroll
                for (int p = 0; p < 5; p++) Y = ffma2(wlinp[p], hv[p], Y);
                int bb = warpB0 + gb;
                if (bb < B && t0 + s < outT)
                    out[(size_t)bb * outT + t0 + s] = psum(Y);
            }
        }
    };

    // carried vd = h2(-1) = zeros
    u64 vd[5];
#pragma unroll
    for (int p = 0; p < 5; p++) vd[p] = pack2(0.0f, 0.0f);

    // prologue: commit chunk 0, prefetch chunk 16
    { float a0, a1; ldg_chunk(0, a0, a1); sts_chunk(a0, a1); }
    if (T > 16) ldg_chunk(16, xr0, xr1);

    // gates for step 0 (h1(-1) = 0)
    u64 G0, G1, G2, G3, H0, H1, H2, H3;
    {
        float x0 = sw[SW_X + gc * 20 + 0];
        G0 = pack2(fmaf(wih1[0], x0, b1[0]), 0.0f);
        G1 = pack2(fmaf(wih1[1], x0, b1[1]), 0.0f);
        G2 = pack2(fmaf(wih1[2], x0, b1[2]), 0.0f);
        G3 = pack2(fmaf(wih1[3], x0, b1[3]), 0.0f);
    }

    // one main step: consumes gate regs Gi*, produces Go* (gates for t+1)
    auto step_main = [&](int t,
                         u64& Gi0, u64& Gi1, u64& Gi2, u64& Gi3,
                         u64& Go0, u64& Go1, u64& Go2, u64& Go3) {
        // flush completed y block BEFORE this iter's h2 overwrites slot t&15
        if ((t & 15) == 0 && t > 0) flush_y(t - 16);

        // A = b2 + Whh2 . h2(t-1) from carried vd (3-address init from b2p)
        u64 A0 = ffma2(whh2[0][0], vd[0], b2p[0]);
        u64 A1 = ffma2(whh2[1][0], vd[0], b2p[1]);
        u64 A2 = ffma2(whh2[2][0], vd[0], b2p[2]);
        u64 A3 = ffma2(whh2[3][0], vd[0], b2p[3]);
#pragma unroll
        for (int p = 1; p < 5; p++) {
            A0 = ffma2(whh2[0][p], vd[p], A0);
            A1 = ffma2(whh2[1][p], vd[p], A1);
            A2 = ffma2(whh2[2][p], vd[p], A2);
            A3 = ffma2(whh2[3][p], vd[p], A3);
        }

        // layer-1 activation for step t (consumes Gi)
        float h1 = cell_update_h(psum(Gi0), psum(Gi1), psum(Gi2), psum(Gi3), c1);
        if (alane) sw[SW_H1 + gc * 12 + k] = h1;

        // x(t+1): commit prefetched chunk at boundaries, prefetch next;
        // stage x(t+1) into h1 slot[10] (k==0 lane of each group)
        int tn = t + 1;
        if ((tn & 15) == 0) {
            sts_chunk(xr0, xr1);
            int t0n = tn + 16;
            if (t0n < T) ldg_chunk(t0n, xr0, xr1);
        }
        if (alane && k == 0)
            sw[SW_H1 + gc * 12 + 10] = sw[SW_X + gc * 20 + (tn & 15)];

        // shared h1(t)+x(t+1) vector: feeds ih2 (step t) and hh1+ih1 (t+1)
        u64 w[6];
        load_vec12(sw + SW_H1 + gc * 12, w);
        u64 N0 = ffma2(whh1[0][0], w[0], b1p[0]);
        u64 N1 = ffma2(whh1[1][0], w[0], b1p[1]);
        u64 N2 = ffma2(whh1[2][0], w[0], b1p[2]);
        u64 N3 = ffma2(whh1[3][0], w[0], b1p[3]);
        A0 = ffma2(wih2[0][0], w[0], A0);
        A1 = ffma2(wih2[1][0], w[0], A1);
        A2 = ffma2(wih2[2][0], w[0], A2);
        A3 = ffma2(wih2[3][0], w[0], A3);
#pragma unroll
        for (int p = 1; p < 5; p++) {
            A0 = ffma2(wih2[0][p], w[p], A0);
            A1 = ffma2(wih2[1][p], w[p], A1);
            A2 = ffma2(wih2[2][p], w[p], A2);
            A3 = ffma2(wih2[3][p], w[p], A3);
            N0 = ffma2(whh1[0][p], w[p], N0);
            N1 = ffma2(whh1[1][p], w[p], N1);
            N2 = ffma2(whh1[2][p], w[p], N2);
            N3 = ffma2(whh1[3][p], w[p], N3);
        }
        // 6th pair: x(t+1) term for layer-1 gates (weight hi = 0)
        N0 = ffma2(wih1p[0], w[5], N0);
        N1 = ffma2(wih1p[1], w[5], N1);
        N2 = ffma2(wih1p[2], w[5], N2);
        N3 = ffma2(wih1p[3], w[5], N3);
        Go0 = N0; Go1 = N1; Go2 = N2; Go3 = N3;

        // layer-2 activation for step t; store into history slot; re-carry vd
        float h2 = cell_update_h(psum(A0), psum(A1), psum(A2), psum(A3), c2);
        float* hslot = sw + SW_HIST + (t & 15) * 36 + gc * 12;
        if (alane) hslot[k] = h2;
        load_vec10(hslot, vd);
    };

    // ---- pipelined main loop: steps 0 .. T-2, 2x unrolled (G/H roles) ----
    int t = 0;
#pragma unroll 1
    for (; t + 2 <= T - 1; t += 2) {
        step_main(t,     G0, G1, G2, G3, H0, H1, H2, H3);
        step_main(t + 1, H0, H1, H2, H3, G0, G1, G2, G3);
    }
    if (t < T - 1) {
        step_main(t, G0, G1, G2, G3, H0, H1, H2, H3);
        G0 = H0; G1 = H1; G2 = H2; G3 = H3;
    }

    // ---- tail: step T-1 with x[T-1], then future steps with y feedback ----
    float xt = sw[SW_X + gc * 20 + 15];   // x[T-1]
#pragma unroll 1
    for (int tt = T - 1; tt < outT; tt++) {
        u64 w[5];

        // layer 1
        load_vec10(sw + SW_H1 + gc * 12, w);     // h1(t-1)
        u64 g0 = pack2(fmaf(wih1[0], xt, b1[0]), 0.0f);
        u64 g1 = pack2(fmaf(wih1[1], xt, b1[1]), 0.0f);
        u64 g2 = pack2(fmaf(wih1[2], xt, b1[2]), 0.0f);
        u64 g3 = pack2(fmaf(wih1[3], xt, b1[3]), 0.0f);
#pragma unroll
        for (int p = 0; p < 5; p++) {
            g0 = ffma2(whh1[0][p], w[p], g0);
            g1 = ffma2(whh1[1][p], w[p], g1);
            g2 = ffma2(whh1[2][p], w[p], g2);
            g3 = ffma2(whh1[3][p], w[p], g3);
        }
        float h1 = cell_update_h(psum(g0), psum(g1), psum(g2), psum(g3), c1);
        if (alane) sw[SW_H1 + gc * 12 + k] = h1;

        // layer 2 (vd holds h2(t-1))
        load_vec10(sw + SW_H1 + gc * 12, w);     // h1(t)
        u64 a0 = pack2(b2[0], 0.0f), a1 = pack2(b2[1], 0.0f);
        u64 a2 = pack2(b2[2], 0.0f), a3 = pack2(b2[3], 0.0f);
#pragma unroll
        for (int p = 0; p < 5; p++) {
            a0 = ffma2(wih2[0][p], w[p], a0);  a0 = ffma2(whh2[0][p], vd[p], a0);
            a1 = ffma2(wih2[1][p], w[p], a1);  a1 = ffma2(whh2[1][p], vd[p], a1);
            a2 = ffma2(wih2[2][p], w[p], a2);  a2 = ffma2(whh2[2][p], vd[p], a2);
            a3 = ffma2(wih2[3][p], w[p], a3);  a3 = ffma2(whh2[3][p], vd[p], a3);
        }
        float h2 = cell_update_h(psum(a0), psum(a1), psum(a2), psum(a3), c2);
        float* hslot = sw + SW_HIST + (tt & 15) * 36 + gc * 12;
        if (alane) hslot[k] = h2;
        load_vec10(hslot, vd);                   // fresh h2(t)

        // head from fresh h2(t) (feedback value; stored directly when t >= T)
        u64 Y = pack2(blin, 0.0f);
#pragma unroll
        for (int p = 0; p < 5; p++) Y = ffma2(wlinp[p], vd[p], Y);
        float y = psum(Y);
        xt = y;
        if (tt >= T && alane && k == 0 && b < B)
            out[(size_t)b * outT + tt] = y;

        // once h2(T-1) is in slot 15, flush the last main block T-16..T-1
        if (tt == T - 1) flush_y(T - 16);
    }
}

extern "C" void kernel_launch(void* const* d_in, const int* in_sizes, int n_in,
                              void* d_out, int out_size)
{
    const float* x     = (const float*)d_in[0];
    const float* W_ih1 = (const float*)d_in[1];
    const float* W_hh1 = (const float*)d_in[2];
    const float* b_ih1 = (const float*)d_in[3];
    const float* b_hh1 = (const float*)d_in[4];
    const float* W_ih2 = (const float*)d_in[5];
    const float* W_hh2 = (const float*)d_in[6];
    const float* b_ih2 = (const float*)d_in[7];
    const float* b_hh2 = (const float*)d_in[8];
    const float* W_lin = (const float*)d_in[9];
    const float* b_lin = (const float*)d_in[10];
    float* out = (float*)d_out;

    const int T = T_FIXED;
    const int B = in_sizes[0] / T;          // 2048
    const int outT = out_size / B;          // T + future = 1088

    // 3 batches per warp, 4 warps per block -> 12 batches/block (R13 grid)
    const int nWarps  = (B + 2) / 3;                    // 683
    const int nBlocks = (nWarps + 3) / 4;               // 171
    lstm2_seq_kernel<<<nBlocks, 128>>>(
        x, W_ih1, W_hh1, b_ih1, b_hh1,
        W_ih2, W_hh2, b_ih2, b_hh2,
        W_lin, b_lin, out, B, T, outT);
}